// round 3
// baseline (speedup 1.0000x reference)
#include <cuda_runtime.h>
#include <cuda_bf16.h>

// Problem shape (fixed by the dataset): [B=32, C=1, H=1024, W=1024] fp32.
#define B_DIM 32
#define HW (1024 * 1024)
#define HW4 (HW / 4)
#define GRID (HW4 / 256)
#define LAMBDA 0.1

// Global accumulators: [0]=diff2, [1]=G2, [2]=H2. Zero at module load;
// the last block of each launch resets them to zero for the next replay.
__device__ double g_acc[3];
__device__ unsigned int g_count;

__global__ __launch_bounds__(256) void praloss_fused_kernel(
    const float4* __restrict__ est, const float4* __restrict__ gt,
    float* __restrict__ out)
{
    const int pix4 = blockIdx.x * blockDim.x + threadIdx.x;  // 0 .. HW4-1

    float4 s_e = make_float4(0.f, 0.f, 0.f, 0.f);
    float4 s_g = make_float4(0.f, 0.f, 0.f, 0.f);
    float4 q_e = make_float4(0.f, 0.f, 0.f, 0.f);
    float4 q_d = make_float4(0.f, 0.f, 0.f, 0.f);

    #pragma unroll 8
    for (int b = 0; b < B_DIM; b++) {
        const float4 e = est[(long)b * HW4 + pix4];
        const float4 g = gt [(long)b * HW4 + pix4];
        s_e.x += e.x; s_e.y += e.y; s_e.z += e.z; s_e.w += e.w;
        s_g.x += g.x; s_g.y += g.y; s_g.z += g.z; s_g.w += g.w;
        q_e.x = fmaf(e.x, e.x, q_e.x);
        q_e.y = fmaf(e.y, e.y, q_e.y);
        q_e.z = fmaf(e.z, e.z, q_e.z);
        q_e.w = fmaf(e.w, e.w, q_e.w);
        float dx = e.x - g.x, dy = e.y - g.y, dz = e.z - g.z, dw = e.w - g.w;
        q_d.x = fmaf(dx, dx, q_d.x);
        q_d.y = fmaf(dy, dy, q_d.y);
        q_d.z = fmaf(dz, dz, q_d.z);
        q_d.w = fmaf(dw, dw, q_d.w);
    }

    float diff2 = q_d.x + q_d.y + q_d.z + q_d.w;
    float G2    = q_e.x + q_e.y + q_e.z + q_e.w;
    float H2    = (s_e.x > s_g.x ? q_e.x : 0.f)
                + (s_e.y > s_g.y ? q_e.y : 0.f)
                + (s_e.z > s_g.z ? q_e.z : 0.f)
                + (s_e.w > s_g.w ? q_e.w : 0.f);

    // Warp reduce (3 scalars)
    #pragma unroll
    for (int off = 16; off > 0; off >>= 1) {
        diff2 += __shfl_down_sync(0xFFFFFFFFu, diff2, off);
        G2    += __shfl_down_sync(0xFFFFFFFFu, G2,    off);
        H2    += __shfl_down_sync(0xFFFFFFFFu, H2,    off);
    }

    // Block reduce via shared memory (8 warps)
    __shared__ float sm[3][8];
    const int lane = threadIdx.x & 31;
    const int wid  = threadIdx.x >> 5;
    if (lane == 0) {
        sm[0][wid] = diff2; sm[1][wid] = G2; sm[2][wid] = H2;
    }
    __syncthreads();

    if (threadIdx.x == 0) {
        float v0 = 0.f, v1 = 0.f, v2 = 0.f;
        #pragma unroll
        for (int w = 0; w < 8; w++) {
            v0 += sm[0][w]; v1 += sm[1][w]; v2 += sm[2][w];
        }
        atomicAdd(&g_acc[0], (double)v0);
        atomicAdd(&g_acc[1], (double)v1);
        atomicAdd(&g_acc[2], (double)v2);

        // Make this block's atomics visible, then take a ticket.
        __threadfence();
        unsigned int old = atomicAdd(&g_count, 1u);
        if (old == (unsigned int)(GRID - 1)) {
            // Last block: all other blocks' atomics are L2-visible.
            double diff2d = atomicAdd(&g_acc[0], 0.0);
            double G2d    = atomicAdd(&g_acc[1], 0.0);
            double H2d    = atomicAdd(&g_acc[2], 0.0);
            out[0] = (float)(diff2d / G2d + LAMBDA * (diff2d / H2d));
            // Reset state for the next graph replay (we are the only
            // block still running; stream order protects the next launch).
            atomicExch((unsigned long long*)&g_acc[0], 0ull);
            atomicExch((unsigned long long*)&g_acc[1], 0ull);
            atomicExch((unsigned long long*)&g_acc[2], 0ull);
            __threadfence();
            atomicExch(&g_count, 0u);
        }
    }
}

extern "C" void kernel_launch(void* const* d_in, const int* in_sizes, int n_in,
                              void* d_out, int out_size) {
    const float4* est = (const float4*)d_in[0];
    const float4* gt  = (const float4*)d_in[1];
    float* out = (float*)d_out;

    praloss_fused_kernel<<<GRID, 256>>>(est, gt, out);
}